// round 3
// baseline (speedup 1.0000x reference)
#include <cuda_runtime.h>
#include <cstdint>

#define N_NODES 1000000
#define N_EDGES 5000000

// Scratch (static device globals -- no allocation allowed)
__device__ float g_deg[N_NODES];
__device__ float g_dinv[N_NODES];
__device__ float g_xs[N_NODES];   // x * dinv   (layer-1 source values)
__device__ float g_ys[N_NODES];   // h2 * dinv  (layer-2 source values)
__device__ float g_S[N_NODES];    // scatter accumulator (reused both layers)
__device__ int   g_is64;          // 1 if edge_index is int64, 0 if int32

// ---------------------------------------------------------------------------
// init: deg = 1 (self loop), plus dtype detection in block 0.
// int32 data misread as int64 yields values >= 2^32 with overwhelming prob.
__global__ void k_init(const long long* __restrict__ ei) {
    if (blockIdx.x == 0 && threadIdx.x < 64) {
        if (threadIdx.x == 0) g_is64 = 1;
        __syncwarp();
        long long v = ei[threadIdx.x];
        if (v < 0 || v >= (long long)N_NODES) g_is64 = 0;
    }
    unsigned i = blockIdx.x * blockDim.x + threadIdx.x;
    if (i < N_NODES / 4)
        ((float4*)g_deg)[i] = make_float4(1.f, 1.f, 1.f, 1.f);
}

// ---------------------------------------------------------------------------
// degree scatter: deg[dst] += 1.  16 edges/thread, batched index loads.
__global__ void __launch_bounds__(512) k_deg(const void* __restrict__ ei) {
    unsigned t = blockIdx.x * blockDim.x + threadIdx.x;
    if (t >= N_EDGES / 16) return;                    // 5M % 16 == 0
    unsigned base = t * 16u;
    int d[16];
    if (g_is64) {
        const longlong2* p = (const longlong2*)((const long long*)ei + N_EDGES) + (base >> 1);
        #pragma unroll
        for (int k = 0; k < 8; k++) {
            longlong2 v = p[k];
            d[2*k]   = (int)v.x;
            d[2*k+1] = (int)v.y;
        }
    } else {
        const int4* p = (const int4*)((const int*)ei + N_EDGES) + (base >> 2);
        #pragma unroll
        for (int k = 0; k < 4; k++) {
            int4 v = p[k];
            d[4*k] = v.x; d[4*k+1] = v.y; d[4*k+2] = v.z; d[4*k+3] = v.w;
        }
    }
    #pragma unroll
    for (int k = 0; k < 16; k++) atomicAdd(&g_deg[d[k]], 1.0f);
}

// ---------------------------------------------------------------------------
// node pass 1: dinv = rsqrt(deg), xs = x * dinv, S = 0.  float4.
__global__ void k_node1(const float* __restrict__ x) {
    unsigned i = blockIdx.x * blockDim.x + threadIdx.x;
    if (i < N_NODES / 4) {
        float4 dg = ((const float4*)g_deg)[i];
        float4 xv = ((const float4*)x)[i];
        float4 dv;
        dv.x = rsqrtf(dg.x); dv.y = rsqrtf(dg.y);
        dv.z = rsqrtf(dg.z); dv.w = rsqrtf(dg.w);
        ((float4*)g_dinv)[i] = dv;
        ((float4*)g_xs)[i] = make_float4(xv.x*dv.x, xv.y*dv.y, xv.z*dv.z, xv.w*dv.w);
        ((float4*)g_S)[i]  = make_float4(0.f, 0.f, 0.f, 0.f);
    }
}

// ---------------------------------------------------------------------------
// edge scatter: S[dst] += vals[src].  8 edges/thread, all loads front-batched.
template <int WHICH>   // 0: vals = g_xs, 1: vals = g_ys
__global__ void __launch_bounds__(512) k_scatter(const void* __restrict__ ei) {
    unsigned t = blockIdx.x * blockDim.x + threadIdx.x;
    if (t >= N_EDGES / 8) return;                     // 5M % 8 == 0
    unsigned base = t * 8u;
    int s[8], d[8];
    if (g_is64) {
        const longlong2* ps = (const longlong2*)((const long long*)ei) + (base >> 1);
        const longlong2* pd = (const longlong2*)((const long long*)ei + N_EDGES) + (base >> 1);
        #pragma unroll
        for (int k = 0; k < 4; k++) {
            longlong2 a = ps[k];
            s[2*k] = (int)a.x; s[2*k+1] = (int)a.y;
        }
        #pragma unroll
        for (int k = 0; k < 4; k++) {
            longlong2 a = pd[k];
            d[2*k] = (int)a.x; d[2*k+1] = (int)a.y;
        }
    } else {
        const int4* ps = (const int4*)((const int*)ei) + (base >> 2);
        const int4* pd = (const int4*)((const int*)ei + N_EDGES) + (base >> 2);
        #pragma unroll
        for (int k = 0; k < 2; k++) {
            int4 a = ps[k];
            s[4*k] = a.x; s[4*k+1] = a.y; s[4*k+2] = a.z; s[4*k+3] = a.w;
        }
        #pragma unroll
        for (int k = 0; k < 2; k++) {
            int4 a = pd[k];
            d[4*k] = a.x; d[4*k+1] = a.y; d[4*k+2] = a.z; d[4*k+3] = a.w;
        }
    }
    const float* vals = WHICH ? g_ys : g_xs;
    float v[8];
    #pragma unroll
    for (int k = 0; k < 8; k++) v[k] = __ldg(&vals[s[k]]);   // 8 independent gathers
    #pragma unroll
    for (int k = 0; k < 8; k++) atomicAdd(&g_S[d[k]], v[k]);
}

// ---------------------------------------------------------------------------
// node pass 2: agg1 -> relu/W2 fold -> ys; re-zero S.  float4.
__global__ void k_node2(const float* __restrict__ W1,
                        const float* __restrict__ b1,
                        const float* __restrict__ W2) {
    unsigned i = blockIdx.x * blockDim.x + threadIdx.x;
    if (i >= N_NODES / 4) return;

    float w1[16], bb[16], w2[16];
    #pragma unroll
    for (int f = 0; f < 16; f++) { w1[f] = W1[f]; bb[f] = b1[f]; w2[f] = W2[f]; }

    float4 Sv  = ((const float4*)g_S)[i];
    float4 xsv = ((const float4*)g_xs)[i];
    float4 dv  = ((const float4*)g_dinv)[i];

    float agg[4] = { dv.x*(Sv.x+xsv.x), dv.y*(Sv.y+xsv.y),
                     dv.z*(Sv.z+xsv.z), dv.w*(Sv.w+xsv.w) };
    float h2[4] = {0.f, 0.f, 0.f, 0.f};
    #pragma unroll
    for (int f = 0; f < 16; f++) {
        #pragma unroll
        for (int j = 0; j < 4; j++)
            h2[j] += fmaxf(fmaf(agg[j], w1[f], bb[f]), 0.0f) * w2[f];
    }
    ((float4*)g_ys)[i] = make_float4(h2[0]*dv.x, h2[1]*dv.y, h2[2]*dv.z, h2[3]*dv.w);
    ((float4*)g_S)[i]  = make_float4(0.f, 0.f, 0.f, 0.f);
}

// ---------------------------------------------------------------------------
// node pass 3: out = dinv*(S + ys) + b2.  float4.
__global__ void k_node3(float* __restrict__ out, const float* __restrict__ b2) {
    unsigned i = blockIdx.x * blockDim.x + threadIdx.x;
    if (i < N_NODES / 4) {
        float bias = b2[0];
        float4 Sv = ((const float4*)g_S)[i];
        float4 yv = ((const float4*)g_ys)[i];
        float4 dv = ((const float4*)g_dinv)[i];
        ((float4*)out)[i] = make_float4(fmaf(dv.x, Sv.x + yv.x, bias),
                                        fmaf(dv.y, Sv.y + yv.y, bias),
                                        fmaf(dv.z, Sv.z + yv.z, bias),
                                        fmaf(dv.w, Sv.w + yv.w, bias));
    }
}

// ---------------------------------------------------------------------------
extern "C" void kernel_launch(void* const* d_in, const int* in_sizes, int n_in,
                              void* d_out, int out_size) {
    const float* x  = (const float*)d_in[0];
    const void*  ei = d_in[1];
    const float* W1 = (const float*)d_in[2];
    const float* b1 = (const float*)d_in[3];
    const float* W2 = (const float*)d_in[4];
    const float* b2 = (const float*)d_in[5];
    float* out = (float*)d_out;

    const int TB = 256;
    const int node4Blocks = (N_NODES / 4 + TB - 1) / TB;
    const int deg16Blocks = (N_EDGES / 16 + 511) / 512;
    const int sc8Blocks   = (N_EDGES / 8 + 511) / 512;

    k_init<<<node4Blocks, TB>>>((const long long*)ei);
    k_deg<<<deg16Blocks, 512>>>(ei);
    k_node1<<<node4Blocks, TB>>>(x);
    k_scatter<0><<<sc8Blocks, 512>>>(ei);
    k_node2<<<node4Blocks, TB>>>(W1, b1, W2);
    k_scatter<1><<<sc8Blocks, 512>>>(ei);
    k_node3<<<node4Blocks, TB>>>(out, b2);
}